// round 1
// baseline (speedup 1.0000x reference)
#include <cuda_runtime.h>
#include <math.h>

// Problem constants (fixed by reference: point_cloud [8, 4096, 3], K=20)
#define BATCH 8
#define NPTS  4096
#define KNN   20
#define TPB   128
#define CHUNKS (NPTS / TPB)   // 32 chunks per batch -> grid = 8*32 = 256 CTAs

__global__ __launch_bounds__(TPB)
void knn_graph_kernel(const float* __restrict__ pc, float* __restrict__ out)
{
    // SoA point storage for the whole batch: 3 * 4096 * 4B = 48 KB
    __shared__ float xs[NPTS];
    __shared__ float ys[NPTS];
    __shared__ float zs[NPTS];

    const int b     = blockIdx.x / CHUNKS;
    const int chunk = blockIdx.x % CHUNKS;
    const float* __restrict__ pcb = pc + (size_t)b * NPTS * 3;

    // Coalesced load + deinterleave into SoA
    for (int t = threadIdx.x; t < NPTS * 3; t += TPB) {
        float v = pcb[t];
        int j = t / 3;
        int c = t - 3 * j;
        if (c == 0)      xs[j] = v;
        else if (c == 1) ys[j] = v;
        else             zs[j] = v;
    }
    __syncthreads();

    const int qi = chunk * TPB + threadIdx.x;   // query index within batch
    const float qx = xs[qi], qy = ys[qi], qz = zs[qi];

    // Sorted top-K (ascending d2) in registers
    float bd[KNN];
    int   bi[KNN];
#pragma unroll
    for (int k = 0; k < KNN; k++) { bd[k] = 3.0e38f; bi[k] = 0; }

#pragma unroll 4
    for (int j = 0; j < NPTS; j++) {
        float dx = xs[j] - qx;
        float dy = ys[j] - qy;
        float dz = zs[j] - qz;
        float d2 = fmaf(dx, dx, fmaf(dy, dy, dz * dz));
        if (j == qi) d2 = 3.9e38f;                // self-exclusion

        if (d2 < bd[KNN - 1]) {                   // passes current k-th distance
            float c = d2; int ci = j;
            if (c >= bd[KNN / 2 - 1]) {
                // lands in upper half: bubble only slots 10..19
#pragma unroll
                for (int k = KNN / 2; k < KNN; k++) {
                    bool  p  = c < bd[k];
                    float tv = bd[k]; int ti = bi[k];
                    bd[k] = p ? c  : bd[k];
                    bi[k] = p ? ci : bi[k];
                    c     = p ? tv : c;
                    ci    = p ? ti : ci;
                }
            } else {
                // full bubble through all 20 slots
#pragma unroll
                for (int k = 0; k < KNN; k++) {
                    bool  p  = c < bd[k];
                    float tv = bd[k]; int ti = bi[k];
                    bd[k] = p ? c  : bd[k];
                    bi[k] = p ? ci : bi[k];
                    c     = p ? tv : c;
                    ci    = p ? ti : ci;
                }
            }
        }
    }

    // ---- epilogue: emit outputs --------------------------------------
    // Output buffer layout (float32, reference tuple flattened in order):
    //   [0,            BNK)   edge_indices row 0 (src)
    //   [BNK,        2*BNK)   edge_indices row 1 (tgt)
    //   [2*BNK,      3*BNK)   edge_attrs
    //   [3*BNK, 3*BNK+B*N)    s_local
    const long long BNK = (long long)BATCH * NPTS * KNN;
    const int row = b * NPTS + qi;

    float dk     = sqrtf(bd[KNN - 1]);            // distance to k-th NN
    float sigma  = dk + 1e-6f;                    // BETA = 1
    float inv2s2 = 1.0f / (2.0f * sigma * sigma);

    float* __restrict__ src  = out;
    float* __restrict__ tgt  = out + BNK;
    float* __restrict__ attr = out + 2 * BNK;
    float* __restrict__ sloc = out + 3 * BNK;

    const long long base = (long long)row * KNN;
    const float rowf  = (float)row;
    const float boffs = (float)(b * NPTS);
#pragma unroll
    for (int k = 0; k < KNN; k++) {
        src[base + k]  = rowf;
        tgt[base + k]  = boffs + (float)bi[k];
        attr[base + k] = expf(-bd[k] * inv2s2);
    }
    sloc[row] = dk * dk;                          // LAMBDA = 1, d_i^2
}

extern "C" void kernel_launch(void* const* d_in, const int* in_sizes, int n_in,
                              void* d_out, int out_size)
{
    (void)in_sizes; (void)n_in; (void)out_size;
    const float* pc = (const float*)d_in[0];
    float* out = (float*)d_out;
    knn_graph_kernel<<<BATCH * CHUNKS, TPB>>>(pc, out);
}

// round 3
// speedup vs baseline: 1.2909x; 1.2909x over previous
#include <cuda_runtime.h>
#include <math.h>

// Problem constants (fixed: point_cloud [8, 4096, 3], K=20)
#define BATCH 8
#define NPTS  4096
#define KNN   20
#define KS    25            // approx top-25 kept: true top-21 (self+20) guaranteed inside
#define KE    21            // exact list: self + 20 neighbors
#define TPB   128
#define CHUNKS (NPTS / TPB) // 32 -> grid = 256 CTAs

__global__ __launch_bounds__(TPB)
void knn_graph_kernel(const float* __restrict__ pc, float* __restrict__ out)
{
    // Whole batch staged as float4 (x, y, z, |p|^2): 4096*16B = 64KB dynamic smem.
    extern __shared__ float4 pts[];

    const int b     = blockIdx.x / CHUNKS;
    const int chunk = blockIdx.x % CHUNKS;
    const float* __restrict__ pcb = pc + (size_t)b * NPTS * 3;

    for (int i = threadIdx.x; i < NPTS; i += TPB) {
        float x = pcb[3 * i + 0];
        float y = pcb[3 * i + 1];
        float z = pcb[3 * i + 2];
        float w = fmaf(x, x, fmaf(y, y, z * z));
        pts[i] = make_float4(x, y, z, w);
    }
    __syncthreads();

    const int qi = chunk * TPB + threadIdx.x;
    const float4 q = pts[qi];
    const float n2qx = -2.0f * q.x, n2qy = -2.0f * q.y, n2qz = -2.0f * q.z;
    const float sqq = q.w;

    // Approx sorted list of packed keys:
    //   key = round_to_nearest_12bit(d2 float bits) | candidate_index (12 bits)
    // Positive-float bit order == float order; rounding errors are healed by the
    // exact epilogue below (margin of 4 extra slots guarantees membership).
    unsigned key[KS];
#pragma unroll
    for (int k = 0; k < KS; k++) key[k] = 0xFFFFFFFFu;

#pragma unroll 8
    for (int j = 0; j < NPTS; j++) {
        float4 p = pts[j];                       // one LDS.128, warp-broadcast
        // d2 = |p|^2 - 2 q.p + |q|^2  (same expansion as the reference), clamped
        float t  = fmaf(n2qz, p.z, p.w);
        t        = fmaf(n2qy, p.y, t);
        t        = fmaf(n2qx, p.x, t);
        float d2 = fmaxf(t + sqq, 0.0f);
        unsigned kb = (((__float_as_uint(d2) + 0x800u) & 0xFFFFF000u) | (unsigned)j);

        if (kb < key[KS - 1]) {                  // beats current worst
            unsigned c = kb;
            if (c >= key[KS / 2]) {
#pragma unroll
                for (int k = KS / 2 + 1; k < KS; k++) {
                    unsigned tt = key[k];
                    key[k] = min(c, tt);         // IMNMX.U32
                    c      = max(c, tt);
                }
            } else {
#pragma unroll
                for (int k = 0; k < KS; k++) {
                    unsigned tt = key[k];
                    key[k] = min(c, tt);
                    c      = max(c, tt);
                }
            }
        }
    }

    // ---- exact fixup: re-rank the 25 survivors with full-precision d2 ----
    float fd[KE];
    int   fi[KE];
#pragma unroll
    for (int k = 0; k < KE; k++) { fd[k] = 3.0e38f; fi[k] = 0; }

#pragma unroll
    for (int s = 0; s < KS; s++) {
        int id = (int)(key[s] & 0xFFFu);
        float4 p = pts[id];
        float t  = fmaf(n2qz, p.z, p.w);
        t        = fmaf(n2qy, p.y, t);
        t        = fmaf(n2qx, p.x, t);
        float d2 = fmaxf(t + sqq, 0.0f);
        if (d2 < fd[KE - 1]) {
            float c = d2; int ci = id;
#pragma unroll
            for (int k = 0; k < KE; k++) {
                bool  pbit = c < fd[k];          // strict: stable for exact ties
                float tv = fd[k]; int ti = fi[k];
                fd[k] = pbit ? c  : fd[k];
                fi[k] = pbit ? ci : fi[k];
                c     = pbit ? tv : c;
                ci    = pbit ? ti : ci;
            }
        }
    }
    // Slot 0 is self (d2 ~ 0, far below any true neighbor); neighbors = 1..20.

    // ---- emit outputs ------------------------------------------------
    const long long BNK = (long long)BATCH * NPTS * KNN;
    const int row = b * NPTS + qi;

    float dk     = sqrtf(fd[KE - 1]);
    float sigma  = dk + 1e-6f;                 // BETA = 1
    float inv2s2 = 1.0f / (2.0f * sigma * sigma);

    float* __restrict__ src  = out;
    float* __restrict__ tgt  = out + BNK;
    float* __restrict__ attr = out + 2 * BNK;
    float* __restrict__ sloc = out + 3 * BNK;

    const long long base = (long long)row * KNN;
    const float rowf  = (float)row;
    const float boffs = (float)(b * NPTS);
#pragma unroll
    for (int k = 0; k < KNN; k++) {
        src[base + k]  = rowf;
        tgt[base + k]  = boffs + (float)fi[k + 1];
        attr[base + k] = expf(-fd[k + 1] * inv2s2);
    }
    sloc[row] = dk * dk;                       // LAMBDA = 1
}

extern "C" void kernel_launch(void* const* d_in, const int* in_sizes, int n_in,
                              void* d_out, int out_size)
{
    (void)in_sizes; (void)n_in; (void)out_size;
    const float* pc = (const float*)d_in[0];
    float* outp = (float*)d_out;

    const size_t smem = (size_t)NPTS * sizeof(float4);   // 64 KB
    cudaFuncSetAttribute(knn_graph_kernel,
                         cudaFuncAttributeMaxDynamicSharedMemorySize, (int)smem);
    knn_graph_kernel<<<BATCH * CHUNKS, TPB, smem>>>(pc, outp);
}